// round 10
// baseline (speedup 1.0000x reference)
#include <cuda_runtime.h>

// CTC forward loss — linear DP w/ per-lane block-floating-point; producer warp
// pre-gathers per-lane emissions into smem (conflict-free LDS for the DP).
// B=128, T=1024, C=128 (blank=127), L=128, S=257.
//
// One CTA (64 threads) per batch element.
//   warp 1 (producer): per row t -> (a) Z-sum for the softmax normalizer,
//     (b) gathered float4 {p[t,labels[4l..4l+3]]+eps} to gbuf[t&63][l] for
//     every DP lane l, (c) p_blank+eps to pbv[t&63]. Stays 32 rows ahead.
//   warp 0 (DP): lane l owns states 8l..8l+7 (+256 on lane 31). Per step:
//     one LDS.128 (stride 16B, conflict-free) + one broadcast LDS.32.
//     Renorm every 4 steps, Round-7 timing: fold sck into er[PH^1] (row t+1),
//     sc_pm switches right after this step's pm1 — single scale frame always.
//   Sync: one __syncthreads per 16-step phase.
//
// loglik = log(a255+a256) + e*ln2 - zsum  (lane 31);  out = -loglik.

#define T_   1024
#define C_   128
#define L_   128
#define EPS_ 1e-7f
#define CEPS_ (128.0f * 1e-7f)
#define FULL 0xffffffffu
#define RMASK 63

// ---------------- producer: 16 rows starting at r0 ----------------
__device__ __forceinline__ void produce16(const float* __restrict__ row,
                                          float4* __restrict__ gq,
                                          float* __restrict__ pbv,
                                          int g, int il, int lane,
                                          int cls0, int cls1, int cls2, int cls3,
                                          int r0, float& zs)
{
    // (a) Z-sums: 4 rows in flight, 8 lanes per row
    float zp = 1.f;
#pragma unroll
    for (int rr = 0; rr < 4; ++rr) {
        const int r = r0 + rr * 4 + g;
        const float* p = row + (size_t)r * C_ + il * 16;
        float4 v0 = *(const float4*)(p);
        float4 v1 = *(const float4*)(p + 4);
        float4 v2 = *(const float4*)(p + 8);
        float4 v3 = *(const float4*)(p + 12);
        float s = (((v0.x + v0.y) + (v0.z + v0.w))
                 + ((v1.x + v1.y) + (v1.z + v1.w)))
                + (((v2.x + v2.y) + (v2.z + v2.w))
                 + ((v3.x + v3.y) + (v3.z + v3.w)));
        s += __shfl_xor_sync(FULL, s, 1);
        s += __shfl_xor_sync(FULL, s, 2);
        s += __shfl_xor_sync(FULL, s, 4);
        zp *= (s + CEPS_);                 // sum(p) + C*eps
    }
    zs += __logf(zp);                      // <=16 factors of <=~64+: no overflow

    // (b,c) gathered emissions for every DP lane (L1 hits: rows just streamed)
#pragma unroll
    for (int rr = 0; rr < 16; ++rr) {
        const int r = r0 + rr;
        const float* rp = row + (size_t)r * C_;
        float4 gv;
        gv.x = rp[cls0] + EPS_;
        gv.y = rp[cls1] + EPS_;
        gv.z = rp[cls2] + EPS_;
        gv.w = rp[cls3] + EPS_;
        gq[(size_t)(r & RMASK) * 32 + lane] = gv;
        if (lane == 0) pbv[r & RMASK] = rp[C_ - 1] + EPS_;
    }
}

// One DP timestep. PH = t&1 (register ring slot), RS = renorm, LD = LDS t+2.
// pm1 for t+1 uses the OLD sc_pm (computed before RS); RS folds sck into
// er[PH^1]/erb[PH^1] (row t+1's emissions) and then updates sc_pm.
#define STEP(PH, t, RS, LD) {                                                  \
    const float4 q = er[PH];                                                   \
    const float pb = erb[PH];                                                  \
    if (LD) {                                                                  \
        er[PH]  = gq[(size_t)(((t) + 2) & RMASK) * 32 + lane];                 \
        erb[PH] = pbv[((t) + 2) & RMASK];                                      \
    }                                                                          \
    const float n0 = (a0 + pm1) * pb;                                          \
    const float n1 = fmaf(sk0, pm1, a1 + a0) * q.x;                            \
    const float n2 = (a2 + a1) * pb;                                           \
    const float n3 = fmaf(sk1, a1, a3 + a2) * q.y;                             \
    const float n4 = (a4 + a3) * pb;                                           \
    const float n5 = fmaf(sk2, a3, a5 + a4) * q.z;                             \
    const float n6 = (a6 + a5) * pb;                                           \
    const float n7 = fmaf(sk3, a5, a7 + a6) * q.w;                             \
    const float n8 = (a256 + a7) * pb;   /* lane31: a7 == alpha[255] */        \
    a0 = n0; a1 = n1; a2 = n2; a3 = n3;                                        \
    a4 = n4; a5 = n5; a6 = n6; a7 = n7; a256 = n8;                             \
    pm1 = __shfl_up_sync(FULL, a7, 1) * sc_pm;   /* old sc_pm: for t+1 */      \
    if (RS) {                                                                  \
        float m = fmaxf(fmaxf(fmaxf(n0, n1), fmaxf(n2, n3)),                   \
                        fmaxf(fmaxf(n4, n5), fmaxf(n6, n7)));                  \
        if (lane == 31) m = fmaxf(m, n8);                                      \
        const int e_up_old = __shfl_up_sync(FULL, e, 1);                       \
        const bool has = (m > 0.f);                                            \
        const int k = has ? ((__float_as_int(m) >> 23) - 127) : 0;             \
        const float sck = __int_as_float((127 - k) << 23);                     \
        er[PH ^ 1].x *= sck; er[PH ^ 1].y *= sck;                              \
        er[PH ^ 1].z *= sck; er[PH ^ 1].w *= sck;                              \
        erb[PH ^ 1]  *= sck;                                                   \
        e = has ? (e + k) : e_up_old;    /* empty lane adopts neighbor */      \
        const int e_up2 = __shfl_up_sync(FULL, e, 1);                          \
        const int bexp = min(max(e_up2 - e + 127, 0), 254);                    \
        sc_pm = (lane == 0) ? 0.f : __int_as_float(bexp << 23);                \
    } }

// 16 steps; RS at j%4==3, PH = j&1 (tb even), LD=1.
#define BLK16(tb)                                                              \
    STEP(0, (tb)+0,  0,1) STEP(1, (tb)+1,  0,1)                                \
    STEP(0, (tb)+2,  0,1) STEP(1, (tb)+3,  1,1)                                \
    STEP(0, (tb)+4,  0,1) STEP(1, (tb)+5,  0,1)                                \
    STEP(0, (tb)+6,  0,1) STEP(1, (tb)+7,  1,1)                                \
    STEP(0, (tb)+8,  0,1) STEP(1, (tb)+9,  0,1)                                \
    STEP(0, (tb)+10, 0,1) STEP(1, (tb)+11, 1,1)                                \
    STEP(0, (tb)+12, 0,1) STEP(1, (tb)+13, 0,1)                                \
    STEP(0, (tb)+14, 0,1) STEP(1, (tb)+15, 1,1)

// Last block: no LDS past row 1023, no final renorm at t=1023.
#define BLK16_LAST(tb)                                                         \
    STEP(0, (tb)+0,  0,1) STEP(1, (tb)+1,  0,1)                                \
    STEP(0, (tb)+2,  0,1) STEP(1, (tb)+3,  1,1)                                \
    STEP(0, (tb)+4,  0,1) STEP(1, (tb)+5,  0,1)                                \
    STEP(0, (tb)+6,  0,1) STEP(1, (tb)+7,  1,1)                                \
    STEP(0, (tb)+8,  0,1) STEP(1, (tb)+9,  0,1)                                \
    STEP(0, (tb)+10, 0,1) STEP(1, (tb)+11, 1,1)                                \
    STEP(0, (tb)+12, 0,1) STEP(1, (tb)+13, 0,1)                                \
    STEP(0, (tb)+14, 0,0) STEP(1, (tb)+15, 0,0)

__global__ __launch_bounds__(64, 1)
void ctc_gather_kernel(const int* __restrict__ y_true,
                       const float* __restrict__ y_pred,
                       float* __restrict__ out)
{
    __shared__ float4 gq[64 * 32];    // 32 KB: gathered per-lane emissions
    __shared__ float  pbv[64];        // blank+eps per ring row
    __shared__ float  s_zsum;

    const int b    = blockIdx.x;
    const int tid  = threadIdx.x;
    const int lane = tid & 31;
    const int wrp  = tid >> 5;
    const float* __restrict__ row = y_pred + (size_t)b * T_ * C_;

    // ---- per-lane label config (both warps need it) ----
    int4 c4 = *(const int4*)(y_true + b * L_ + 4 * lane);
    const int cls0 = c4.x, cls1 = c4.y, cls2 = c4.z, cls3 = c4.w;
    int clsm1 = __shfl_up_sync(FULL, cls3, 1);
    const float sk0 = (lane > 0 && cls0 != clsm1) ? 1.f : 0.f;
    const float sk1 = (cls1 != cls0) ? 1.f : 0.f;
    const float sk2 = (cls2 != cls1) ? 1.f : 0.f;
    const float sk3 = (cls3 != cls2) ? 1.f : 0.f;

    const int g  = lane >> 3;
    const int il = lane & 7;
    float zs = 0.f;

    // DP state
    float4 er[2];
    float  erb[2];
    float a0 = 0.f, a1 = 0.f, a2 = 0.f, a3 = 0.f,
          a4 = 0.f, a5 = 0.f, a6 = 0.f, a7 = 0.f, a256 = 0.f;
    int   e = 0;
    float sc_pm = (lane == 0) ? 0.f : 1.f;
    float pm1 = 0.f;
    float fin_a = 0.f, fin_c = 0.f;
    int   fin_e = 0;

    // ---- prime: producer stages rows 0..31 ----
    if (wrp == 1) {
        produce16(row, gq, pbv, g, il, lane, cls0, cls1, cls2, cls3, 0,  zs);
        produce16(row, gq, pbv, g, il, lane, cls0, cls1, cls2, cls3, 16, zs);
    }
    __syncthreads();

    // ---- phase 0: DP t=0..15; producer rows 32..47 ----
    if (wrp == 1) {
        produce16(row, gq, pbv, g, il, lane, cls0, cls1, cls2, cls3, 32, zs);
    } else {
        er[0]  = gq[lane];            erb[0] = pbv[0];
        er[1]  = gq[32 + lane];       erb[1] = pbv[1];
        // t = 0: init states 0 (blank) and 1 (first label); refill slot 0
        if (lane == 0) { a0 = erb[0]; a1 = er[0].x; }
        er[0]  = gq[2 * 32 + lane];   erb[0] = pbv[2];
        // pm1 stays 0 (all a7 == 0 at t=0)
        STEP(1, 1,  0,1) STEP(0, 2,  0,1) STEP(1, 3,  1,1)
        STEP(0, 4,  0,1) STEP(1, 5,  0,1) STEP(0, 6,  0,1) STEP(1, 7,  1,1)
        STEP(0, 8,  0,1) STEP(1, 9,  0,1) STEP(0, 10, 0,1) STEP(1, 11, 1,1)
        STEP(0, 12, 0,1) STEP(1, 13, 0,1) STEP(0, 14, 0,1) STEP(1, 15, 1,1)
    }
    __syncthreads();

    // ---- phases 1..62 ----
    for (int kk = 1; kk < 63; ++kk) {
        if (wrp == 1) {
            if (kk <= 61)
                produce16(row, gq, pbv, g, il, lane,
                          cls0, cls1, cls2, cls3, 16 * kk + 32, zs);
        } else {
            const int tb = 16 * kk;
            BLK16(tb)
        }
        __syncthreads();
    }

    // ---- phase 63: final DP block; producer folds its normalizer ----
    if (wrp == 0) {
        BLK16_LAST(1008)
        fin_a = a7;      // alpha[255] on lane 31 (scale 2^e)
        fin_c = a256;    // alpha[256] on lane 31
        fin_e = e;
    } else {
        zs += __shfl_xor_sync(FULL, zs, 8);
        zs += __shfl_xor_sync(FULL, zs, 16);
        if (lane == 0) s_zsum = zs;
    }
    __syncthreads();

    if (tid == 31) {   // warp 0, lane 31
        float ll = __logf(fin_a + fin_c) + (float)fin_e * 0.6931471805599453f
                   - s_zsum;
        out[b] = -ll;
    }
}

extern "C" void kernel_launch(void* const* d_in, const int* in_sizes, int n_in,
                              void* d_out, int out_size)
{
    const int* y_true;
    const float* y_pred;
    if (in_sizes[0] == 128 * L_) {            // y_true: [B,L] int32
        y_true = (const int*)d_in[0];
        y_pred = (const float*)d_in[1];
    } else {
        y_true = (const int*)d_in[1];
        y_pred = (const float*)d_in[0];
    }
    const int B = out_size;                    // [B,1] float32
    ctc_gather_kernel<<<B, 64>>>(y_true, y_pred, (float*)d_out);
}

// round 11
// speedup vs baseline: 1.4144x; 1.4144x over previous
#include <cuda_runtime.h>

// CTC forward loss — linear-domain DP, per-lane block-floating-point scaling.
// B=128, T=1024, C=128 (blank=127), L=128, S=257.
//
// One CTA (64 threads) per batch element.
//   warp 0: sequential DP, lane l owns states 8l..8l+7 (+256 on lane 31).
//           true_alpha = a * 2^e. pm1 prepared one step ahead (shfl hidden).
//           Emission ring holds RAW LDG results (no math attached to the
//           load) — eps is added at CONSUME time, 8 steps (~800 cyc) after
//           the LDG issues, so no long-scoreboard stall is ever exposed.
//           Renorm every 4 steps (at t%4==3); its scale sckq is applied to
//           the NEXT consumed emissions (steps t%4==0) — same timing as the
//           Round-7 register fold, just expressed at consume.
//   warp 1: softmax log-normalizer, quarter-warp-per-row layout.
//
// loglik = log(a255+a256) + e*ln2 - zsum  (lane 31);  out = -loglik.

#define T_   1024
#define C_   128
#define L_   128
#define EPS_ 1e-7f
#define CEPS_ (128.0f * 1e-7f)
#define FULL 0xffffffffu

// One DP timestep. PH = ring slot, RS = renorm, RF = refill (raw LDG only),
// SC = scale consumed emissions by sckq (first step after a renorm).
#define STEP(PH, t, RS, RF, SC) {                                              \
    float q0 = gbr[PH][0] + EPS_, q1 = gbr[PH][1] + EPS_,                      \
          q2 = gbr[PH][2] + EPS_, q3 = gbr[PH][3] + EPS_,                      \
          pb = pbr[PH] + EPS_;                                                 \
    if (SC) { q0 *= sckq; q1 *= sckq; q2 *= sckq; q3 *= sckq; pb *= sckq; }    \
    if (RF) {                                                                  \
        const float* r8 = row + (size_t)((t) + 8) * C_;                        \
        gbr[PH][0] = r8[cls0]; gbr[PH][1] = r8[cls1];                          \
        gbr[PH][2] = r8[cls2]; gbr[PH][3] = r8[cls3];                          \
        pbr[PH]    = r8[C_ - 1];                                               \
    }                                                                          \
    const float n0 = (a0 + pm1) * pb;                                          \
    const float n1 = fmaf(sk0, pm1, a1 + a0) * q0;                             \
    const float n2 = (a2 + a1) * pb;                                           \
    const float n3 = fmaf(sk1, a1, a3 + a2) * q1;                              \
    const float n4 = (a4 + a3) * pb;                                           \
    const float n5 = fmaf(sk2, a3, a5 + a4) * q2;                              \
    const float n6 = (a6 + a5) * pb;                                           \
    const float n7 = fmaf(sk3, a5, a7 + a6) * q3;                              \
    const float n8 = (a256 + a7) * pb;   /* lane31: a7 == alpha[255] */        \
    a0 = n0; a1 = n1; a2 = n2; a3 = n3;                                        \
    a4 = n4; a5 = n5; a6 = n6; a7 = n7; a256 = n8;                             \
    pm1 = __shfl_up_sync(FULL, a7, 1) * sc_pm;   /* old sc_pm: for t+1 */      \
    if (RS) {                                                                  \
        float m = fmaxf(fmaxf(fmaxf(n0, n1), fmaxf(n2, n3)),                   \
                        fmaxf(fmaxf(n4, n5), fmaxf(n6, n7)));                  \
        if (lane == 31) m = fmaxf(m, n8);                                      \
        const int e_up_old = __shfl_up_sync(FULL, e, 1);                       \
        const bool has = (m > 0.f);                                            \
        const int k = has ? ((__float_as_int(m) >> 23) - 127) : 0;             \
        sckq = __int_as_float((127 - k) << 23);  /* applied at next SC step */ \
        e = has ? (e + k) : e_up_old;    /* empty lane adopts neighbor */      \
        const int e_up2 = __shfl_up_sync(FULL, e, 1);                          \
        const int bexp = min(max(e_up2 - e + 127, 0), 254);                    \
        sc_pm = (lane == 0) ? 0.f : __int_as_float(bexp << 23);                \
    } }

// 8 steps; renorm at j%4==3, scale-apply at j%4==0.
#define BLOCK8(tb, RF) \
    STEP(0, (tb) + 0, 0, RF, 1) STEP(1, (tb) + 1, 0, RF, 0) \
    STEP(2, (tb) + 2, 0, RF, 0) STEP(3, (tb) + 3, 1, RF, 0) \
    STEP(4, (tb) + 4, 0, RF, 1) STEP(5, (tb) + 5, 0, RF, 0) \
    STEP(6, (tb) + 6, 0, RF, 0) STEP(7, (tb) + 7, 1, RF, 0)

// Final block: no refills, no renorm at t=1023 (outputs stay at the scale set
// by the t=1019 renorm, which is applied at t=1020's SC).
#define BLOCK8_LAST(tb) \
    STEP(0, (tb) + 0, 0, 0, 1) STEP(1, (tb) + 1, 0, 0, 0) \
    STEP(2, (tb) + 2, 0, 0, 0) STEP(3, (tb) + 3, 1, 0, 0) \
    STEP(4, (tb) + 4, 0, 0, 1) STEP(5, (tb) + 5, 0, 0, 0) \
    STEP(6, (tb) + 6, 0, 0, 0) STEP(7, (tb) + 7, 0, 0, 0)

__global__ __launch_bounds__(64, 1)
void ctc_raw_kernel(const int* __restrict__ y_true,
                    const float* __restrict__ y_pred,
                    float* __restrict__ out)
{
    const int b    = blockIdx.x;
    const int tid  = threadIdx.x;
    const int lane = tid & 31;
    const int wrp  = tid >> 5;
    const float* __restrict__ row = y_pred + (size_t)b * T_ * C_;

    __shared__ float s_zsum;

    float fin_a = 0.f, fin_c = 0.f;
    int   fin_e = 0;

    if (wrp == 1) {
        // -------- softmax log-normalizer: 4 rows per round --------
        const int g  = lane >> 3;
        const int il = lane & 7;
        const float* zrow = row + (size_t)g * C_ + (size_t)il * 16;

        float4 ring[4][4];
        #pragma unroll
        for (int j = 0; j < 4; j++) {
            const float* p = zrow + (size_t)j * 4 * C_;
            ring[j][0] = *(const float4*)(p + 0);
            ring[j][1] = *(const float4*)(p + 4);
            ring[j][2] = *(const float4*)(p + 8);
            ring[j][3] = *(const float4*)(p + 12);
        }

        float zs = 0.f;
        for (int r8 = 0; r8 < 256; r8 += 8) {
            float zp = 1.f;
            #pragma unroll
            for (int rr = 0; rr < 8; rr++) {
                const int slot = rr & 3;
                float4 v0 = ring[slot][0], v1 = ring[slot][1],
                       v2 = ring[slot][2], v3 = ring[slot][3];
                const int r = r8 + rr;
                if (r + 4 < 256) {
                    const float* p = zrow + (size_t)(r + 4) * 4 * C_;
                    ring[slot][0] = *(const float4*)(p + 0);
                    ring[slot][1] = *(const float4*)(p + 4);
                    ring[slot][2] = *(const float4*)(p + 8);
                    ring[slot][3] = *(const float4*)(p + 12);
                }
                float s = ((v0.x + v0.y) + (v0.z + v0.w))
                        + ((v1.x + v1.y) + (v1.z + v1.w))
                        + ((v2.x + v2.y) + (v2.z + v2.w))
                        + ((v3.x + v3.y) + (v3.z + v3.w));
                s += __shfl_xor_sync(FULL, s, 1);
                s += __shfl_xor_sync(FULL, s, 2);
                s += __shfl_xor_sync(FULL, s, 4);
                zp *= (s + CEPS_);
            }
            zs += __logf(zp);
        }
        zs += __shfl_xor_sync(FULL, zs, 8);
        zs += __shfl_xor_sync(FULL, zs, 16);
        if (lane == 0) s_zsum = zs;
    } else {
        // -------- sequential DP warp --------
        int4 c4 = *(const int4*)(y_true + b * L_ + 4 * lane);
        const int cls0 = c4.x, cls1 = c4.y, cls2 = c4.z, cls3 = c4.w;
        int clsm1 = __shfl_up_sync(FULL, cls3, 1);
        const float sk0 = (lane > 0 && cls0 != clsm1) ? 1.f : 0.f;
        const float sk1 = (cls1 != cls0) ? 1.f : 0.f;
        const float sk2 = (cls2 != cls1) ? 1.f : 0.f;
        const float sk3 = (cls3 != cls2) ? 1.f : 0.f;

        // prefetch ring, depth 8: RAW values (eps added at consume)
        float gbr[8][4];
        float pbr[8];
        #pragma unroll
        for (int j = 0; j < 8; j++) {
            const float* r = row + (size_t)j * C_;
            gbr[j][0] = r[cls0]; gbr[j][1] = r[cls1];
            gbr[j][2] = r[cls2]; gbr[j][3] = r[cls3];
            pbr[j]    = r[C_ - 1];
        }

        float a0 = 0.f, a1 = 0.f, a2 = 0.f, a3 = 0.f,
              a4 = 0.f, a5 = 0.f, a6 = 0.f, a7 = 0.f, a256 = 0.f;
        int   e = 0;
        float sckq = 1.f;
        float sc_pm, pm1;

        // ---- t = 0 init: states 0 (blank) and 1 (first label) ----
        {
            if (lane == 0) { a0 = pbr[0] + EPS_; a1 = gbr[0][0] + EPS_; }
            const float* r8 = row + (size_t)8 * C_;   // refill slot 0 (raw)
            gbr[0][0] = r8[cls0]; gbr[0][1] = r8[cls1];
            gbr[0][2] = r8[cls2]; gbr[0][3] = r8[cls3];
            pbr[0]    = r8[C_ - 1];
            sc_pm = (lane == 0) ? 0.f : 1.0f;
            pm1 = __shfl_up_sync(FULL, a7, 1) * sc_pm;   // = 0
        }

        // ---- t = 1..7 prologue (renorm t=3,7; apply at t=4) ----
        STEP(1, 1, 0, 1, 0) STEP(2, 2, 0, 1, 0) STEP(3, 3, 1, 1, 0)
        STEP(4, 4, 0, 1, 1) STEP(5, 5, 0, 1, 0) STEP(6, 6, 0, 1, 0)
        STEP(7, 7, 1, 1, 0)

        // ---- t = 8..1015: refills in range (t+8 <= 1023) ----
        for (int tb = 8; tb < 1016; tb += 8) {
            BLOCK8(tb, 1)
        }
        // ---- t = 1016..1023: no refills, no final renorm ----
        BLOCK8_LAST(1016)

        fin_a = a7;      // alpha[255] on lane 31 (scale 2^e)
        fin_c = a256;    // alpha[256] on lane 31
        fin_e = e;
    }

    __syncthreads();
    if (wrp == 0 && lane == 31) {
        float ll = __logf(fin_a + fin_c) + (float)fin_e * 0.6931471805599453f
                   - s_zsum;
        out[b] = -ll;
    }
}

extern "C" void kernel_launch(void* const* d_in, const int* in_sizes, int n_in,
                              void* d_out, int out_size)
{
    const int* y_true;
    const float* y_pred;
    if (in_sizes[0] == 128 * L_) {            // y_true: [B,L] int32
        y_true = (const int*)d_in[0];
        y_pred = (const float*)d_in[1];
    } else {
        y_true = (const int*)d_in[1];
        y_pred = (const float*)d_in[0];
    }
    const int B = out_size;                    // [B,1] float32
    ctc_raw_kernel<<<B, 64>>>(y_true, y_pred, (float*)d_out);
}

// round 12
// speedup vs baseline: 1.5485x; 1.0948x over previous
#include <cuda_runtime.h>

// CTC forward loss — linear-domain DP, per-lane block-floating-point scaling.
// B=128, T=1024, C=128 (blank=127), L=128, S=257.
//
// One CTA (64 threads) per batch element.
//   warp 0: sequential DP, lane l owns states 8l..8l+7 (+256 on lane 31).
//           true_alpha = a * 2^e. Emission ring holds RAW LDG results;
//           the eps-add (and renorm-scale fold) is SOFTWARE-PIPELINED: step t
//           prepares step t+1's operand registers, so every step starts with
//           all operands ready. n7 (the recurrence) is computed first and its
//           shfl issued immediately. Renorm every 4 steps with a SINGLE shfl:
//           the adoption value for empty lanes is the shfl result saved from
//           the previous renorm (e only changes at renorms).
//   warp 1: softmax log-normalizer, quarter-warp-per-row layout.
//
// loglik = log(a255+a256) + e*ln2 - zsum  (lane 31);  out = -loglik.

#define T_   1024
#define C_   128
#define L_   128
#define EPS_ 1e-7f
#define CEPS_ (128.0f * 1e-7f)
#define FULL 0xffffffffu

// One DP timestep. PH = ring slot (= t&7), RS = renorm, RF = refill (raw LDG),
// PREP = prepare next step's operand registers.
#define STEP(PH, t, RS, RF, PREP) {                                            \
    const float n7 = fmaf(sk3, a5, a7 + a6) * cq3;   /* recurrence first */    \
    const float a7s = __shfl_up_sync(FULL, n7, 1);   /* issue shfl early */    \
    const float n8 = (a256 + a7) * cpb;                                        \
    const float n0 = (a0 + pm1) * cpb;                                         \
    const float n1 = fmaf(sk0, pm1, a1 + a0) * cq0;                            \
    const float n2 = (a2 + a1) * cpb;                                          \
    const float n3 = fmaf(sk1, a1, a3 + a2) * cq1;                             \
    const float n4 = (a4 + a3) * cpb;                                          \
    const float n5 = fmaf(sk2, a3, a5 + a4) * cq2;                             \
    const float n6 = (a6 + a5) * cpb;                                          \
    if (RF) {                                                                  \
        const float* r8 = row + (size_t)((t) + 8) * C_;                        \
        gbr[PH][0] = r8[cls0]; gbr[PH][1] = r8[cls1];                          \
        gbr[PH][2] = r8[cls2]; gbr[PH][3] = r8[cls3];                          \
        pbr[PH]    = r8[C_ - 1];                                               \
    }                                                                          \
    a0 = n0; a1 = n1; a2 = n2; a3 = n3;                                        \
    a4 = n4; a5 = n5; a6 = n6; a7 = n7; a256 = n8;                             \
    float sckq = 1.f;                                                          \
    if (RS) {                                                                  \
        float m = fmaxf(fmaxf(fmaxf(n0, n1), fmaxf(n2, n3)),                   \
                        fmaxf(fmaxf(n4, n5), fmaxf(n6, n7)));                  \
        m = fmaxf(m, n8);            /* any consistent scale is valid */       \
        const bool has = (m > 0.f);                                            \
        const int k = has ? ((__float_as_int(m) >> 23) - 127) : 0;             \
        sckq = __int_as_float((127 - k) << 23);                                \
        e = has ? (e + k) : e_up_save;   /* adoption: pre-renorm nbr e */      \
        e_up_save = __shfl_up_sync(FULL, e, 1);  /* the ONLY renorm shfl */    \
        const int bexp = min(max(e_up_save - e + 127, 0), 254);                \
        sc_pm_nx = (lane == 0) ? 0.f : __int_as_float(bexp << 23);             \
    }                                                                          \
    pm1 = a7s * sc_pm;               /* OLD sc_pm: scale frame of step t */    \
    if (RS) sc_pm = sc_pm_nx;                                                  \
    if (PREP) {                      /* prepare step t+1's operands */         \
        const int NP = ((t) + 1) & 7;                                          \
        cq0 = gbr[NP][0] + EPS_; cq1 = gbr[NP][1] + EPS_;                      \
        cq2 = gbr[NP][2] + EPS_; cq3 = gbr[NP][3] + EPS_;                      \
        cpb = pbr[NP] + EPS_;                                                  \
        if (RS) { cq0 *= sckq; cq1 *= sckq; cq2 *= sckq;                       \
                  cq3 *= sckq; cpb *= sckq; }                                  \
    } }

#define BLOCK8(tb) \
    STEP(0, (tb) + 0, 0, 1, 1) STEP(1, (tb) + 1, 0, 1, 1) \
    STEP(2, (tb) + 2, 0, 1, 1) STEP(3, (tb) + 3, 1, 1, 1) \
    STEP(4, (tb) + 4, 0, 1, 1) STEP(5, (tb) + 5, 0, 1, 1) \
    STEP(6, (tb) + 6, 0, 1, 1) STEP(7, (tb) + 7, 1, 1, 1)

// Final block: no refills, renorm only at t=1019 (its scale lands at the
// t=1019 prep for step 1020), no renorm/prep at t=1023.
#define BLOCK8_LAST(tb) \
    STEP(0, (tb) + 0, 0, 0, 1) STEP(1, (tb) + 1, 0, 0, 1) \
    STEP(2, (tb) + 2, 0, 0, 1) STEP(3, (tb) + 3, 1, 0, 1) \
    STEP(4, (tb) + 4, 0, 0, 1) STEP(5, (tb) + 5, 0, 0, 1) \
    STEP(6, (tb) + 6, 0, 0, 1) STEP(7, (tb) + 7, 0, 0, 0)

__global__ __launch_bounds__(64, 1)
void ctc_sp_kernel(const int* __restrict__ y_true,
                   const float* __restrict__ y_pred,
                   float* __restrict__ out)
{
    const int b    = blockIdx.x;
    const int tid  = threadIdx.x;
    const int lane = tid & 31;
    const int wrp  = tid >> 5;
    const float* __restrict__ row = y_pred + (size_t)b * T_ * C_;

    __shared__ float s_zsum;

    float fin_a = 0.f, fin_c = 0.f;
    int   fin_e = 0;

    if (wrp == 1) {
        // -------- softmax log-normalizer: 4 rows per round --------
        const int g  = lane >> 3;
        const int il = lane & 7;
        const float* zrow = row + (size_t)g * C_ + (size_t)il * 16;

        float4 ring[4][4];
        #pragma unroll
        for (int j = 0; j < 4; j++) {
            const float* p = zrow + (size_t)j * 4 * C_;
            ring[j][0] = *(const float4*)(p + 0);
            ring[j][1] = *(const float4*)(p + 4);
            ring[j][2] = *(const float4*)(p + 8);
            ring[j][3] = *(const float4*)(p + 12);
        }

        float zs = 0.f;
        for (int r8 = 0; r8 < 256; r8 += 8) {
            float zp = 1.f;
            #pragma unroll
            for (int rr = 0; rr < 8; rr++) {
                const int slot = rr & 3;
                float4 v0 = ring[slot][0], v1 = ring[slot][1],
                       v2 = ring[slot][2], v3 = ring[slot][3];
                const int r = r8 + rr;
                if (r + 4 < 256) {
                    const float* p = zrow + (size_t)(r + 4) * 4 * C_;
                    ring[slot][0] = *(const float4*)(p + 0);
                    ring[slot][1] = *(const float4*)(p + 4);
                    ring[slot][2] = *(const float4*)(p + 8);
                    ring[slot][3] = *(const float4*)(p + 12);
                }
                float s = ((v0.x + v0.y) + (v0.z + v0.w))
                        + ((v1.x + v1.y) + (v1.z + v1.w))
                        + ((v2.x + v2.y) + (v2.z + v2.w))
                        + ((v3.x + v3.y) + (v3.z + v3.w));
                s += __shfl_xor_sync(FULL, s, 1);
                s += __shfl_xor_sync(FULL, s, 2);
                s += __shfl_xor_sync(FULL, s, 4);
                zp *= (s + CEPS_);
            }
            zs += __logf(zp);
        }
        zs += __shfl_xor_sync(FULL, zs, 8);
        zs += __shfl_xor_sync(FULL, zs, 16);
        if (lane == 0) s_zsum = zs;
    } else {
        // -------- sequential DP warp --------
        int4 c4 = *(const int4*)(y_true + b * L_ + 4 * lane);
        const int cls0 = c4.x, cls1 = c4.y, cls2 = c4.z, cls3 = c4.w;
        int clsm1 = __shfl_up_sync(FULL, cls3, 1);
        const float sk0 = (lane > 0 && cls0 != clsm1) ? 1.f : 0.f;
        const float sk1 = (cls1 != cls0) ? 1.f : 0.f;
        const float sk2 = (cls2 != cls1) ? 1.f : 0.f;
        const float sk3 = (cls3 != cls2) ? 1.f : 0.f;

        // prefetch ring, depth 8: RAW values (eps added at prep)
        float gbr[8][4];
        float pbr[8];
        #pragma unroll
        for (int j = 0; j < 8; j++) {
            const float* r = row + (size_t)j * C_;
            gbr[j][0] = r[cls0]; gbr[j][1] = r[cls1];
            gbr[j][2] = r[cls2]; gbr[j][3] = r[cls3];
            pbr[j]    = r[C_ - 1];
        }

        float a0 = 0.f, a1 = 0.f, a2 = 0.f, a3 = 0.f,
              a4 = 0.f, a5 = 0.f, a6 = 0.f, a7 = 0.f, a256 = 0.f;
        int   e = 0, e_up_save = 0;
        float sc_pm = (lane == 0) ? 0.f : 1.f;
        float sc_pm_nx = sc_pm;
        float pm1 = 0.f;
        float cq0, cq1, cq2, cq3, cpb;

        // ---- t = 0 init: states 0 (blank) and 1 (first label) ----
        {
            cq0 = gbr[0][0] + EPS_;
            cpb = pbr[0] + EPS_;
            if (lane == 0) { a0 = cpb; a1 = cq0; }
            const float* r8 = row + (size_t)8 * C_;   // refill slot 0 (raw)
            gbr[0][0] = r8[cls0]; gbr[0][1] = r8[cls1];
            gbr[0][2] = r8[cls2]; gbr[0][3] = r8[cls3];
            pbr[0]    = r8[C_ - 1];
            // prep operands for t = 1
            cq0 = gbr[1][0] + EPS_; cq1 = gbr[1][1] + EPS_;
            cq2 = gbr[1][2] + EPS_; cq3 = gbr[1][3] + EPS_;
            cpb = pbr[1] + EPS_;
            // pm1 stays 0 (all a7 == 0 at t=0)
        }

        // ---- t = 1..7 prologue (renorm t=3,7) ----
        STEP(1, 1, 0, 1, 1) STEP(2, 2, 0, 1, 1) STEP(3, 3, 1, 1, 1)
        STEP(4, 4, 0, 1, 1) STEP(5, 5, 0, 1, 1) STEP(6, 6, 0, 1, 1)
        STEP(7, 7, 1, 1, 1)

        // ---- t = 8..1015: refills in range (t+8 <= 1023) ----
        for (int tb = 8; tb < 1016; tb += 8) {
            BLOCK8(tb)
        }
        // ---- t = 1016..1023 ----
        BLOCK8_LAST(1016)

        fin_a = a7;      // alpha[255] on lane 31 (scale 2^e)
        fin_c = a256;    // alpha[256] on lane 31
        fin_e = e;
    }

    __syncthreads();
    if (wrp == 0 && lane == 31) {
        float ll = __logf(fin_a + fin_c) + (float)fin_e * 0.6931471805599453f
                   - s_zsum;
        out[b] = -ll;
    }
}

extern "C" void kernel_launch(void* const* d_in, const int* in_sizes, int n_in,
                              void* d_out, int out_size)
{
    const int* y_true;
    const float* y_pred;
    if (in_sizes[0] == 128 * L_) {            // y_true: [B,L] int32
        y_true = (const int*)d_in[0];
        y_pred = (const float*)d_in[1];
    } else {
        y_true = (const int*)d_in[1];
        y_pred = (const float*)d_in[0];
    }
    const int B = out_size;                    // [B,1] float32
    ctc_sp_kernel<<<B, 64>>>(y_true, y_pred, (float*)d_out);
}

// round 13
// speedup vs baseline: 2.1202x; 1.3692x over previous
#include <cuda_runtime.h>

// CTC forward loss — forward/backward split: two 512-step DP chains in
// parallel (one warp each), combined at t0=511 via sum_s alpha[s]*beta^[s].
// B=128, T=1024, C=128 (blank=127), L=128, S=257.
//
// One CTA (128 threads = 4 warps) per batch element:
//   warp 0: FORWARD DP over rows 0..511   -> alpha_511 (per-lane BFP scale ea)
//   warp 1: BACKWARD DP over rows 1023..512 -> beta^_511 (per-lane scale eb)
//   warp 2: softmax log-normalizer for rows 0..511
//   warp 3: softmax log-normalizer for rows 512..1023
// Combine: loglik = log(sum_l 2^(ea_l+eb_l) * dot_l) - zsum;  out = -loglik.
//
// Both DPs use: raw-LDG 8-deep emission ring, software-pipelined operand prep
// (eps + renorm-scale fold applied one step ahead), renorm every 4 steps with
// per-lane exponents, single-shfl exponent bookkeeping, cross-lane handoff
// pipelined one step ahead (shfl latency hidden).

#define T_   1024
#define C_   128
#define L_   128
#define EPS_ 1e-7f
#define CEPS_ (128.0f * 1e-7f)
#define FULL 0xffffffffu
#define LN2  0.6931471805599453f

// ---------------- FORWARD step (round-12 proven) ----------------
#define FSTEP(PH, t, RS, RF, PREP) {                                           \
    const float n7 = fmaf(sk3, a5, a7 + a6) * cq3;                             \
    const float a7s = __shfl_up_sync(FULL, n7, 1);                             \
    const float n8 = (a256 + a7) * cpb;                                        \
    const float n0 = (a0 + pm1) * cpb;                                         \
    const float n1 = fmaf(sk0, pm1, a1 + a0) * cq0;                            \
    const float n2 = (a2 + a1) * cpb;                                          \
    const float n3 = fmaf(sk1, a1, a3 + a2) * cq1;                             \
    const float n4 = (a4 + a3) * cpb;                                          \
    const float n5 = fmaf(sk2, a3, a5 + a4) * cq2;                             \
    const float n6 = (a6 + a5) * cpb;                                          \
    if (RF) {                                                                  \
        const float* r8 = row + (size_t)((t) + 8) * C_;                        \
        gbr[PH][0] = r8[cls0]; gbr[PH][1] = r8[cls1];                          \
        gbr[PH][2] = r8[cls2]; gbr[PH][3] = r8[cls3];                          \
        pbr[PH]    = r8[C_ - 1];                                               \
    }                                                                          \
    a0 = n0; a1 = n1; a2 = n2; a3 = n3;                                        \
    a4 = n4; a5 = n5; a6 = n6; a7 = n7; a256 = n8;                             \
    float sckq = 1.f;                                                          \
    if (RS) {                                                                  \
        float m = fmaxf(fmaxf(fmaxf(n0, n1), fmaxf(n2, n3)),                   \
                        fmaxf(fmaxf(n4, n5), fmaxf(n6, n7)));                  \
        m = fmaxf(m, n8);                                                      \
        const bool has = (m > 0.f);                                            \
        const int k = has ? ((__float_as_int(m) >> 23) - 127) : 0;             \
        sckq = __int_as_float((127 - k) << 23);                                \
        e = has ? (e + k) : e_up_save;                                         \
        e_up_save = __shfl_up_sync(FULL, e, 1);                                \
        const int bexp = min(max(e_up_save - e + 127, 0), 254);                \
        sc_pm_nx = (lane == 0) ? 0.f : __int_as_float(bexp << 23);             \
    }                                                                          \
    pm1 = a7s * sc_pm;                                                         \
    if (RS) sc_pm = sc_pm_nx;                                                  \
    if (PREP) {                                                                \
        const int NP = ((t) + 1) & 7;                                          \
        cq0 = gbr[NP][0] + EPS_; cq1 = gbr[NP][1] + EPS_;                      \
        cq2 = gbr[NP][2] + EPS_; cq3 = gbr[NP][3] + EPS_;                      \
        cpb = pbr[NP] + EPS_;                                                  \
        if (RS) { cq0 *= sckq; cq1 *= sckq; cq2 *= sckq;                       \
                  cq3 *= sckq; cpb *= sckq; }                                  \
    } }

#define FBLK8(tb) \
    FSTEP(0,(tb)+0,0,1,1) FSTEP(1,(tb)+1,0,1,1) FSTEP(2,(tb)+2,0,1,1) \
    FSTEP(3,(tb)+3,1,1,1) FSTEP(4,(tb)+4,0,1,1) FSTEP(5,(tb)+5,0,1,1) \
    FSTEP(6,(tb)+6,0,1,1) FSTEP(7,(tb)+7,1,1,1)
#define FBLK8_LAST(tb) \
    FSTEP(0,(tb)+0,0,0,1) FSTEP(1,(tb)+1,0,0,1) FSTEP(2,(tb)+2,0,0,1) \
    FSTEP(3,(tb)+3,1,0,1) FSTEP(4,(tb)+4,0,0,1) FSTEP(5,(tb)+5,0,0,1) \
    FSTEP(6,(tb)+6,0,0,1) FSTEP(7,(tb)+7,0,0,0)

// ---------------- BACKWARD step (mirror) ----------------
// Update u computes beta^ at time 1022-u, consuming row 1023-u (emissions
// prepared one step ahead in dq*/dpb/dqs*). comb (for b7) was prepared at the
// previous step: it contains the emission factor, so it is in the sender's
// NEW scale frame -> sc_cm is switched BEFORE comb is built.
#define BSTEP(SL, u, RS, RF, PREP) {                                           \
    const float b0n = fmaf(dq0, b1, dpb * b0);                                 \
    const float b1n = fmaf(dqs1, b3, fmaf(dpb, b2, dq0 * b1));                 \
    const float b2n = fmaf(dq1, b3, dpb * b2);                                 \
    const float b3n = fmaf(dqs2, b5, fmaf(dpb, b4, dq1 * b3));                 \
    const float b4n = fmaf(dq2, b5, dpb * b4);                                 \
    const float b5n = fmaf(dqs3, b7, fmaf(dpb, b6, dq2 * b5));                 \
    const float b6n = fmaf(dq3, b7, dpb * b6);                                 \
    const float b7n = fmaf(dq3, b7, comb);                                     \
    if (RF) {                                                                  \
        const float* r8 = row + (size_t)(1015 - (u)) * C_;                     \
        dbr[SL][0] = r8[cls0]; dbr[SL][1] = r8[cls1];                          \
        dbr[SL][2] = r8[cls2]; dbr[SL][3] = r8[cls3];                          \
        dpr[SL]    = r8[C_ - 1];                                               \
    }                                                                          \
    b0 = b0n; b1 = b1n; b2 = b2n; b3 = b3n;                                    \
    b4 = b4n; b5 = b5n; b6 = b6n; b7 = b7n; b256 = c256;                       \
    float sckq = 1.f;                                                          \
    if (RS) {                                                                  \
        float m = fmaxf(fmaxf(fmaxf(b0n, b1n), fmaxf(b2n, b3n)),               \
                        fmaxf(fmaxf(b4n, b5n), fmaxf(b6n, b7n)));              \
        m = fmaxf(m, b256);                                                    \
        const bool has = (m > 0.f);                                            \
        const int k = has ? ((__float_as_int(m) >> 23) - 127) : 0;             \
        sckq = __int_as_float((127 - k) << 23);                                \
        eb = has ? (eb + k) : e_dn_save;                                       \
        e_dn_save = __shfl_down_sync(FULL, eb, 1);                             \
        const int bexp = min(max(e_dn_save - eb + 127, 0), 254);               \
        sc_cm = __int_as_float(bexp << 23);                                    \
    }                                                                          \
    if (PREP) {                                                                \
        const int NP = ((u) + 1) & 7;                                          \
        dq0 = dbr[NP][0] + EPS_; dq1 = dbr[NP][1] + EPS_;                      \
        dq2 = dbr[NP][2] + EPS_; dq3 = dbr[NP][3] + EPS_;                      \
        dpb = dpr[NP] + EPS_;                                                  \
        if (RS) { dq0 *= sckq; dq1 *= sckq; dq2 *= sckq;                       \
                  dq3 *= sckq; dpb *= sckq; }                                  \
        dqs1 = sk1 * dq1; dqs2 = sk2 * dq2; dqs3 = sk3 * dq3;                  \
        const float gcomb = fmaf(sk0 * dq0, b1, dpb * b0);                     \
        c256 = dpb * b256;                                                     \
        const float gsh = __shfl_down_sync(FULL, gcomb, 1);                    \
        comb = (lane == 31) ? c256 : gsh * sc_cm;                              \
    } }

#define BBLK8(ub) \
    BSTEP(0,(ub)+0,0,1,1) BSTEP(1,(ub)+1,0,1,1) BSTEP(2,(ub)+2,0,1,1) \
    BSTEP(3,(ub)+3,1,1,1) BSTEP(4,(ub)+4,0,1,1) BSTEP(5,(ub)+5,0,1,1) \
    BSTEP(6,(ub)+6,0,1,1) BSTEP(7,(ub)+7,1,1,1)
#define BBLK8_LAST(ub) \
    BSTEP(0,(ub)+0,0,0,1) BSTEP(1,(ub)+1,0,0,1) BSTEP(2,(ub)+2,0,0,1) \
    BSTEP(3,(ub)+3,1,0,1) BSTEP(4,(ub)+4,0,0,1) BSTEP(5,(ub)+5,0,0,1) \
    BSTEP(6,(ub)+6,0,0,1) BSTEP(7,(ub)+7,0,0,0)

// softmax log-normalizer over 512 rows starting at zrow (already lane-offset)
__device__ __forceinline__ float zhalf(const float* __restrict__ zrow)
{
    float4 ring[4][4];
#pragma unroll
    for (int j = 0; j < 4; j++) {
        const float* p = zrow + (size_t)j * 4 * C_;
        ring[j][0] = *(const float4*)(p + 0);
        ring[j][1] = *(const float4*)(p + 4);
        ring[j][2] = *(const float4*)(p + 8);
        ring[j][3] = *(const float4*)(p + 12);
    }
    float zs = 0.f;
    for (int r8 = 0; r8 < 128; r8 += 8) {
        float zp = 1.f;
#pragma unroll
        for (int rr = 0; rr < 8; rr++) {
            const int slot = rr & 3;
            float4 v0 = ring[slot][0], v1 = ring[slot][1],
                   v2 = ring[slot][2], v3 = ring[slot][3];
            const int r = r8 + rr;
            if (r + 4 < 128) {
                const float* p = zrow + (size_t)(r + 4) * 4 * C_;
                ring[slot][0] = *(const float4*)(p + 0);
                ring[slot][1] = *(const float4*)(p + 4);
                ring[slot][2] = *(const float4*)(p + 8);
                ring[slot][3] = *(const float4*)(p + 12);
            }
            float s = ((v0.x + v0.y) + (v0.z + v0.w))
                    + ((v1.x + v1.y) + (v1.z + v1.w))
                    + ((v2.x + v2.y) + (v2.z + v2.w))
                    + ((v3.x + v3.y) + (v3.z + v3.w));
            s += __shfl_xor_sync(FULL, s, 1);
            s += __shfl_xor_sync(FULL, s, 2);
            s += __shfl_xor_sync(FULL, s, 4);
            zp *= (s + CEPS_);
        }
        zs += __logf(zp);
    }
    zs += __shfl_xor_sync(FULL, zs, 8);
    zs += __shfl_xor_sync(FULL, zs, 16);
    return zs;
}

__global__ __launch_bounds__(128, 1)
void ctc_fb_kernel(const int* __restrict__ y_true,
                   const float* __restrict__ y_pred,
                   float* __restrict__ out)
{
    __shared__ float sb_b[32 * 9];
    __shared__ int   sb_e[32];
    __shared__ float s_z[2];

    const int b    = blockIdx.x;
    const int tid  = threadIdx.x;
    const int lane = tid & 31;
    const int wrp  = tid >> 5;
    const float* __restrict__ row = y_pred + (size_t)b * T_ * C_;

    // per-lane label config (shared by both DP warps)
    int4 c4 = *(const int4*)(y_true + b * L_ + 4 * lane);
    const int cls0 = c4.x, cls1 = c4.y, cls2 = c4.z, cls3 = c4.w;
    int clsm1 = __shfl_up_sync(FULL, cls3, 1);
    const float sk0 = (lane > 0 && cls0 != clsm1) ? 1.f : 0.f;
    const float sk1 = (cls1 != cls0) ? 1.f : 0.f;
    const float sk2 = (cls2 != cls1) ? 1.f : 0.f;
    const float sk3 = (cls3 != cls2) ? 1.f : 0.f;

    // forward DP state (function scope: survives to the combine)
    float a0 = 0.f, a1 = 0.f, a2 = 0.f, a3 = 0.f,
          a4 = 0.f, a5 = 0.f, a6 = 0.f, a7 = 0.f, a256 = 0.f;
    int   e = 0;

    if (wrp == 0) {
        // ---------------- FORWARD: rows 0..511 ----------------
        float gbr[8][4];
        float pbr[8];
#pragma unroll
        for (int j = 0; j < 8; j++) {
            const float* r = row + (size_t)j * C_;
            gbr[j][0] = r[cls0]; gbr[j][1] = r[cls1];
            gbr[j][2] = r[cls2]; gbr[j][3] = r[cls3];
            pbr[j]    = r[C_ - 1];
        }
        int   e_up_save = 0;
        float sc_pm = (lane == 0) ? 0.f : 1.f;
        float sc_pm_nx = sc_pm;
        float pm1 = 0.f;
        float cq0, cq1, cq2, cq3, cpb;

        // t = 0 init
        cq0 = gbr[0][0] + EPS_;
        cpb = pbr[0] + EPS_;
        if (lane == 0) { a0 = cpb; a1 = cq0; }
        {
            const float* r8 = row + (size_t)8 * C_;
            gbr[0][0] = r8[cls0]; gbr[0][1] = r8[cls1];
            gbr[0][2] = r8[cls2]; gbr[0][3] = r8[cls3];
            pbr[0]    = r8[C_ - 1];
        }
        cq0 = gbr[1][0] + EPS_; cq1 = gbr[1][1] + EPS_;
        cq2 = gbr[1][2] + EPS_; cq3 = gbr[1][3] + EPS_;
        cpb = pbr[1] + EPS_;

        // t = 1..7
        FSTEP(1,1,0,1,1) FSTEP(2,2,0,1,1) FSTEP(3,3,1,1,1) FSTEP(4,4,0,1,1)
        FSTEP(5,5,0,1,1) FSTEP(6,6,0,1,1) FSTEP(7,7,1,1,1)
        // t = 8..503
        for (int tb = 8; tb < 504; tb += 8) { FBLK8(tb) }
        // t = 504..511
        FBLK8_LAST(504)
    } else if (wrp == 1) {
        // ---------------- BACKWARD: rows 1023..512 ----------------
        float dbr[8][4];
        float dpr[8];
#pragma unroll
        for (int j = 0; j < 8; j++) {
            const float* r = row + (size_t)(1023 - j) * C_;
            dbr[j][0] = r[cls0]; dbr[j][1] = r[cls1];
            dbr[j][2] = r[cls2]; dbr[j][3] = r[cls3];
            dpr[j]    = r[C_ - 1];
        }
        float b0 = 0.f, b1 = 0.f, b2 = 0.f, b3 = 0.f,
              b4 = 0.f, b5 = 0.f, b6 = 0.f;
        float b7   = (lane == 31) ? 1.f : 0.f;   // beta^_1023[255]
        float b256 = (lane == 31) ? 1.f : 0.f;   // beta^_1023[256]
        int   eb = 0, e_dn_save = 0;
        float sc_cm = 1.f;
        float dq0, dq1, dq2, dq3, dpb, dqs1, dqs2, dqs3;
        float c256, comb;

        // init prep for update u=0 (row 1023, slot 0)
        dq0 = dbr[0][0] + EPS_; dq1 = dbr[0][1] + EPS_;
        dq2 = dbr[0][2] + EPS_; dq3 = dbr[0][3] + EPS_;
        dpb = dpr[0] + EPS_;
        dqs1 = sk1 * dq1; dqs2 = sk2 * dq2; dqs3 = sk3 * dq3;
        {
            const float gcomb = fmaf(sk0 * dq0, b1, dpb * b0);  // = 0
            c256 = dpb * b256;
            const float gsh = __shfl_down_sync(FULL, gcomb, 1);
            comb = (lane == 31) ? c256 : gsh * sc_cm;
        }

        // u = 0..503
        for (int ub = 0; ub < 504; ub += 8) { BBLK8(ub) }
        // u = 504..511
        BBLK8_LAST(504)

        // publish beta^_511 (per-lane scale 2^eb)
        sb_b[lane * 9 + 0] = b0; sb_b[lane * 9 + 1] = b1;
        sb_b[lane * 9 + 2] = b2; sb_b[lane * 9 + 3] = b3;
        sb_b[lane * 9 + 4] = b4; sb_b[lane * 9 + 5] = b5;
        sb_b[lane * 9 + 6] = b6; sb_b[lane * 9 + 7] = b7;
        sb_b[lane * 9 + 8] = b256;
        sb_e[lane] = eb;
    } else if (wrp == 2) {
        float zs = zhalf(row + (size_t)(lane >> 3) * C_ + (size_t)(lane & 7) * 16);
        if (lane == 0) s_z[0] = zs;
    } else {
        float zs = zhalf(row + (size_t)512 * C_
                         + (size_t)(lane >> 3) * C_ + (size_t)(lane & 7) * 16);
        if (lane == 0) s_z[1] = zs;
    }

    __syncthreads();

    // ---------------- combine on warp 0 ----------------
    if (wrp == 0) {
        const float* bb = sb_b + lane * 9;
        float dot = a0 * bb[0] + a1 * bb[1] + a2 * bb[2] + a3 * bb[3]
                  + a4 * bb[4] + a5 * bb[5] + a6 * bb[6] + a7 * bb[7];
        if (lane == 31) dot = fmaf(a256, bb[8], dot);
        const int el = e + sb_e[lane];
        int elm = (dot > 0.f) ? el : -1000000;
        elm = max(elm, __shfl_xor_sync(FULL, elm, 1));
        elm = max(elm, __shfl_xor_sync(FULL, elm, 2));
        elm = max(elm, __shfl_xor_sync(FULL, elm, 4));
        elm = max(elm, __shfl_xor_sync(FULL, elm, 8));
        elm = max(elm, __shfl_xor_sync(FULL, elm, 16));
        const int d = el - elm + 127;
        const float sc = (dot > 0.f && d >= 1) ? __int_as_float(d << 23) : 0.f;
        float s = dot * sc;
        s += __shfl_xor_sync(FULL, s, 1);
        s += __shfl_xor_sync(FULL, s, 2);
        s += __shfl_xor_sync(FULL, s, 4);
        s += __shfl_xor_sync(FULL, s, 8);
        s += __shfl_xor_sync(FULL, s, 16);
        if (lane == 0) {
            float ll = __logf(s) + (float)elm * LN2 - (s_z[0] + s_z[1]);
            out[b] = -ll;
        }
    }
}

extern "C" void kernel_launch(void* const* d_in, const int* in_sizes, int n_in,
                              void* d_out, int out_size)
{
    const int* y_true;
    const float* y_pred;
    if (in_sizes[0] == 128 * L_) {            // y_true: [B,L] int32
        y_true = (const int*)d_in[0];
        y_pred = (const float*)d_in[1];
    } else {
        y_true = (const int*)d_in[1];
        y_pred = (const float*)d_in[0];
    }
    const int B = out_size;                    // [B,1] float32
    ctc_fb_kernel<<<B, 128>>>(y_true, y_pred, (float*)d_out);
}